// round 2
// baseline (speedup 1.0000x reference)
#include <cuda_runtime.h>
#include <math.h>

// Problem constants
#define CDIM   512
#define NTOK   2048
#define BATCH  8
#define NLAYER 5
#define HALF   1024
#define MROWS  (BATCH*NTOK)   // 16384
#define QKVLD  (3*CDIM)       // 1536

// Scratch (device globals: allocation-free rule)
__device__ float g_qkv[(size_t)MROWS * QKVLD];          // 100 MB
__device__ float g_S  [(size_t)BATCH * NTOK * NTOK];    // 134 MB
__device__ float g_y  [(size_t)MROWS * CDIM];           //  32 MB
__device__ float g_h  [(size_t)MROWS * 2*CDIM];         //  64 MB

#define BM 128
#define BN 128
#define BK 16

// ---------------------------------------------------------------------------
// Generic SGEMM: C = A(MxK, ld=K) @ B(KxN, ld=N) + bias[N], epilogues:
//   EPI=0 none, EPI=1 exact GELU, EPI=2 residual add (C += ...)
// ---------------------------------------------------------------------------
template<int EPI>
__global__ __launch_bounds__(256)
void sgemm_bias(const float* __restrict__ A, const float* __restrict__ B,
                const float* __restrict__ bias, float* __restrict__ Cm,
                int M, int Nn, int K)
{
    __shared__ float As[BK][BM + 4];
    __shared__ float Bs[BK][BN];
    const int t  = threadIdx.x;
    const int tx = t & 15, ty = t >> 4;
    const int r0 = blockIdx.y * BM;
    const int c0 = blockIdx.x * BN;

    float acc[8][8];
#pragma unroll
    for (int i = 0; i < 8; i++)
#pragma unroll
        for (int j = 0; j < 8; j++) acc[i][j] = 0.f;

    for (int k0 = 0; k0 < K; k0 += BK) {
        // A tile: 128 rows x 16 k  (transposed store, padded)
#pragma unroll
        for (int i = 0; i < 2; i++) {
            int f = t + i * 256;
            int row = f >> 2, kq = f & 3;
            float4 v = *(const float4*)(A + (size_t)(r0 + row) * K + k0 + kq * 4);
            As[kq*4+0][row] = v.x; As[kq*4+1][row] = v.y;
            As[kq*4+2][row] = v.z; As[kq*4+3][row] = v.w;
        }
        // B tile: 16 k x 128 cols (direct, coalesced)
#pragma unroll
        for (int i = 0; i < 2; i++) {
            int f = t + i * 256;
            int kr = f >> 5, cq = f & 31;
            *(float4*)&Bs[kr][cq*4] =
                *(const float4*)(B + (size_t)(k0 + kr) * Nn + c0 + cq * 4);
        }
        __syncthreads();
#pragma unroll
        for (int k = 0; k < BK; k++) {
            float a[8], b[8];
            *(float4*)&a[0] = *(float4*)&As[k][ty*8];
            *(float4*)&a[4] = *(float4*)&As[k][ty*8+4];
            *(float4*)&b[0] = *(float4*)&Bs[k][tx*8];
            *(float4*)&b[4] = *(float4*)&Bs[k][tx*8+4];
#pragma unroll
            for (int i = 0; i < 8; i++)
#pragma unroll
                for (int j = 0; j < 8; j++) acc[i][j] += a[i] * b[j];
        }
        __syncthreads();
    }

#pragma unroll
    for (int i = 0; i < 8; i++) {
        int r = r0 + ty*8 + i;
#pragma unroll
        for (int j = 0; j < 8; j++) {
            int c = c0 + tx*8 + j;
            float v = acc[i][j] + bias[c];
            if (EPI == 1) v = 0.5f * v * (1.f + erff(v * 0.70710678118654752f));
            float* o = Cm + (size_t)r * Nn + c;
            if (EPI == 2) v += *o;
            *o = v;
        }
    }
}

// ---------------------------------------------------------------------------
// Scores: S[b] = scale * Q_b @ K_b^T  (skip fully-masked tiles)
// Q rows at QKV[b*NTOK*1536 + n*1536 + 0..511], K at +512
// ---------------------------------------------------------------------------
__global__ __launch_bounds__(256)
void scores_kernel(const float* __restrict__ QKV, float* __restrict__ S, float scale)
{
    const int bx = blockIdx.x, by = blockIdx.y, b = blockIdx.z;
    // mask tile skip: top half rows only attend j<HALF; bottom is causal
    if (by < (HALF/BM)) { if (bx >= (HALF/BM)) return; }
    else                { if (bx > by)          return; }

    __shared__ float As[BK][BM + 4];
    __shared__ float Bs[BK][BN + 4];
    const int t  = threadIdx.x;
    const int tx = t & 15, ty = t >> 4;
    const int r0 = by * BM, c0 = bx * BN;
    const float* Q  = QKV + (size_t)b * NTOK * QKVLD;
    const float* Kp = Q + CDIM;

    float acc[8][8];
#pragma unroll
    for (int i = 0; i < 8; i++)
#pragma unroll
        for (int j = 0; j < 8; j++) acc[i][j] = 0.f;

    for (int k0 = 0; k0 < CDIM; k0 += BK) {
#pragma unroll
        for (int i = 0; i < 2; i++) {
            int f = t + i * 256;
            int row = f >> 2, kq = f & 3;
            float4 v = *(const float4*)(Q + (size_t)(r0 + row) * QKVLD + k0 + kq * 4);
            As[kq*4+0][row] = v.x; As[kq*4+1][row] = v.y;
            As[kq*4+2][row] = v.z; As[kq*4+3][row] = v.w;
        }
#pragma unroll
        for (int i = 0; i < 2; i++) {
            int f = t + i * 256;
            int row = f >> 2, kq = f & 3;
            float4 v = *(const float4*)(Kp + (size_t)(c0 + row) * QKVLD + k0 + kq * 4);
            Bs[kq*4+0][row] = v.x; Bs[kq*4+1][row] = v.y;
            Bs[kq*4+2][row] = v.z; Bs[kq*4+3][row] = v.w;
        }
        __syncthreads();
#pragma unroll
        for (int k = 0; k < BK; k++) {
            float a[8], bb[8];
            *(float4*)&a[0]  = *(float4*)&As[k][ty*8];
            *(float4*)&a[4]  = *(float4*)&As[k][ty*8+4];
            *(float4*)&bb[0] = *(float4*)&Bs[k][tx*8];
            *(float4*)&bb[4] = *(float4*)&Bs[k][tx*8+4];
#pragma unroll
            for (int i = 0; i < 8; i++)
#pragma unroll
                for (int j = 0; j < 8; j++) acc[i][j] += a[i] * bb[j];
        }
        __syncthreads();
    }

    float* Sp = S + (size_t)b * NTOK * NTOK;
#pragma unroll
    for (int i = 0; i < 8; i++) {
        int r = r0 + ty*8 + i;
#pragma unroll
        for (int j = 0; j < 8; j++)
            Sp[(size_t)r * NTOK + c0 + tx*8 + j] = acc[i][j] * scale;
    }
}

// ---------------------------------------------------------------------------
// Masked softmax over each row of S (exact: masked entries underflow to 0 in
// the reference since bias = -1000; we skip them and zero-fill).
// ---------------------------------------------------------------------------
__global__ __launch_bounds__(256)
void softmax_kernel(float* __restrict__ S)
{
    const int row = blockIdx.x;             // 0..16383
    const int b = row >> 11, i = row & (NTOK - 1);
    const int limit = (i < HALF) ? HALF : (i + 1);
    float* p = S + (size_t)b * NTOK * NTOK + (size_t)i * NTOK;
    const int t = threadIdx.x;

    float vals[8];
    float m = -1e30f;
#pragma unroll
    for (int j = 0; j < 8; j++) {
        int idx = t + j * 256;
        vals[j] = (idx < limit) ? p[idx] : -1e30f;
        m = fmaxf(m, vals[j]);
    }
    __shared__ float red[256];
    red[t] = m; __syncthreads();
    for (int s = 128; s > 0; s >>= 1) {
        if (t < s) red[t] = fmaxf(red[t], red[t + s]);
        __syncthreads();
    }
    m = red[0]; __syncthreads();

    float sum = 0.f;
#pragma unroll
    for (int j = 0; j < 8; j++) {
        int idx = t + j * 256;
        if (idx < limit) { vals[j] = expf(vals[j] - m); sum += vals[j]; }
        else vals[j] = 0.f;
    }
    red[t] = sum; __syncthreads();
    for (int s = 128; s > 0; s >>= 1) {
        if (t < s) red[t] += red[t + s];
        __syncthreads();
    }
    const float inv = 1.f / red[0];
#pragma unroll
    for (int j = 0; j < 8; j++)
        p[t + j * 256] = vals[j] * inv;     // masked positions get exact 0
}

// ---------------------------------------------------------------------------
// out = S @ V, with reduction truncated per row-block (S is 0 beyond limit)
// V rows at QKV[... + 1024], ld=1536
// ---------------------------------------------------------------------------
__global__ __launch_bounds__(256)
void attnv_kernel(const float* __restrict__ S, const float* __restrict__ QKV,
                  float* __restrict__ out)
{
    const int bx = blockIdx.x, by = blockIdx.y, b = blockIdx.z;
    const int r0 = by * BM, c0 = bx * BN;
    const int kmax = (by < HALF/BM) ? HALF : (r0 + BM);

    __shared__ float As[BK][BM + 4];
    __shared__ float Bs[BK][BN];
    const int t  = threadIdx.x;
    const int tx = t & 15, ty = t >> 4;
    const float* Sp = S + (size_t)b * NTOK * NTOK;
    const float* V  = QKV + (size_t)b * NTOK * QKVLD + 2*CDIM;

    float acc[8][8];
#pragma unroll
    for (int i = 0; i < 8; i++)
#pragma unroll
        for (int j = 0; j < 8; j++) acc[i][j] = 0.f;

    for (int k0 = 0; k0 < kmax; k0 += BK) {
#pragma unroll
        for (int i = 0; i < 2; i++) {
            int f = t + i * 256;
            int row = f >> 2, kq = f & 3;
            float4 v = *(const float4*)(Sp + (size_t)(r0 + row) * NTOK + k0 + kq * 4);
            As[kq*4+0][row] = v.x; As[kq*4+1][row] = v.y;
            As[kq*4+2][row] = v.z; As[kq*4+3][row] = v.w;
        }
#pragma unroll
        for (int i = 0; i < 2; i++) {
            int f = t + i * 256;
            int kr = f >> 5, cq = f & 31;
            *(float4*)&Bs[kr][cq*4] =
                *(const float4*)(V + (size_t)(k0 + kr) * QKVLD + c0 + cq * 4);
        }
        __syncthreads();
#pragma unroll
        for (int k = 0; k < BK; k++) {
            float a[8], bb[8];
            *(float4*)&a[0]  = *(float4*)&As[k][ty*8];
            *(float4*)&a[4]  = *(float4*)&As[k][ty*8+4];
            *(float4*)&bb[0] = *(float4*)&Bs[k][tx*8];
            *(float4*)&bb[4] = *(float4*)&Bs[k][tx*8+4];
#pragma unroll
            for (int i = 0; i < 8; i++)
#pragma unroll
                for (int j = 0; j < 8; j++) acc[i][j] += a[i] * bb[j];
        }
        __syncthreads();
    }

#pragma unroll
    for (int i = 0; i < 8; i++) {
        int r = r0 + ty*8 + i;
#pragma unroll
        for (int j = 0; j < 8; j++)
            out[(size_t)(b * NTOK + r) * CDIM + c0 + tx*8 + j] = acc[i][j];
    }
}

// ---------------------------------------------------------------------------
// LayerNorm (two-pass, matches reference formula, eps=1e-5)
// ---------------------------------------------------------------------------
__global__ __launch_bounds__(256)
void layernorm_kernel(const float* __restrict__ X, const float* __restrict__ g,
                      const float* __restrict__ bta, float* __restrict__ Y)
{
    const int row = blockIdx.x;
    const float* x = X + (size_t)row * CDIM;
    const int t = threadIdx.x;
    float v0 = x[t], v1 = x[t + 256];

    __shared__ float red[256];
    red[t] = v0 + v1; __syncthreads();
    for (int s = 128; s > 0; s >>= 1) {
        if (t < s) red[t] += red[t + s];
        __syncthreads();
    }
    const float mu = red[0] * (1.f / CDIM);
    __syncthreads();

    float d0 = v0 - mu, d1 = v1 - mu;
    red[t] = d0*d0 + d1*d1; __syncthreads();
    for (int s = 128; s > 0; s >>= 1) {
        if (t < s) red[t] += red[t + s];
        __syncthreads();
    }
    const float inv = rsqrtf(red[0] * (1.f / CDIM) + 1e-5f);
    Y[(size_t)row * CDIM + t]       = d0 * inv * g[t]       + bta[t];
    Y[(size_t)row * CDIM + t + 256] = d1 * inv * g[t + 256] + bta[t + 256];
}

// ---------------------------------------------------------------------------
extern "C" void kernel_launch(void* const* d_in, const int* in_sizes, int n_in,
                              void* d_out, int out_size)
{
    const float* x_in  = (const float*)d_in[0];
    const float* qkv_w = (const float*)d_in[1];
    const float* qkv_b = (const float*)d_in[2];
    const float* ln_g  = (const float*)d_in[3];
    const float* ln_b  = (const float*)d_in[4];
    const float* fc1_w = (const float*)d_in[5];
    const float* fc1_b = (const float*)d_in[6];
    const float* fc2_w = (const float*)d_in[7];
    const float* fc2_b = (const float*)d_in[8];
    float* out = (float*)d_out;

    float *qkv, *S, *y, *h;
    cudaGetSymbolAddress((void**)&qkv, g_qkv);
    cudaGetSymbolAddress((void**)&S,   g_S);
    cudaGetSymbolAddress((void**)&y,   g_y);
    cudaGetSymbolAddress((void**)&h,   g_h);

    const float scale = 0.044194173824159216f;   // 512^-0.5
    const dim3 thr(256);

    for (int l = 0; l < NLAYER; l++) {
        const float* src = (l == 0) ? x_in : out;

        // 1. qkv = src @ qkv_w[l] + qkv_b[l]       (16384 x 1536, K=512)
        sgemm_bias<0><<<dim3(QKVLD/BN, MROWS/BM), thr>>>(
            src, qkv_w + (size_t)l*CDIM*QKVLD, qkv_b + (size_t)l*QKVLD,
            qkv, MROWS, QKVLD, CDIM);

        // 2. S = scale * Q K^T (masked tiles skipped)
        scores_kernel<<<dim3(NTOK/BN, NTOK/BM, BATCH), thr>>>(qkv, S, scale);

        // 3. masked softmax rows
        softmax_kernel<<<MROWS, thr>>>(S);

        // 4. x = S @ V  -> out
        attnv_kernel<<<dim3(CDIM/BN, NTOK/BM, BATCH), thr>>>(S, qkv, out);

        // 5. y = LN(x)
        layernorm_kernel<<<MROWS, thr>>>(out, ln_g + (size_t)l*CDIM,
                                         ln_b + (size_t)l*CDIM, y);

        // 6. h = gelu(y @ fc1_w[l] + fc1_b[l])     (16384 x 1024, K=512)
        sgemm_bias<1><<<dim3(2*CDIM/BN, MROWS/BM), thr>>>(
            y, fc1_w + (size_t)l*CDIM*2*CDIM, fc1_b + (size_t)l*2*CDIM,
            h, MROWS, 2*CDIM, CDIM);

        // 7. x += h @ fc2_w[l] + fc2_b[l]          (16384 x 512, K=1024)
        sgemm_bias<2><<<dim3(CDIM/BN, MROWS/BM), thr>>>(
            h, fc2_w + (size_t)l*2*CDIM*CDIM, fc2_b + (size_t)l*CDIM,
            out, MROWS, CDIM, 2*CDIM);
    }
}

// round 5
// speedup vs baseline: 2.1065x; 2.1065x over previous
#include <cuda_runtime.h>
#include <cuda_bf16.h>
#include <math.h>
#include <stdint.h>

typedef __nv_bfloat16 bf16;

#define CDIM   512
#define NTOK   2048
#define BATCH  8
#define NLAYER 5
#define MROWS  16384
#define NN     ((size_t)NTOK*NTOK)

// ---------------- scratch (device globals; allocation-free rule) -----------
__device__ float g_S [(size_t)BATCH*NN];
__device__ bf16  g_sh[(size_t)BATCH*NN];
__device__ bf16  g_sl[(size_t)BATCH*NN];
__device__ bf16  g_qh[(size_t)MROWS*CDIM];
__device__ bf16  g_ql[(size_t)MROWS*CDIM];
__device__ bf16  g_kh[(size_t)MROWS*CDIM];
__device__ bf16  g_kl[(size_t)MROWS*CDIM];
__device__ bf16  g_vth[(size_t)MROWS*CDIM];   // V^T: [b][c][n]
__device__ bf16  g_vtl[(size_t)MROWS*CDIM];
__device__ bf16  g_yh[(size_t)MROWS*CDIM];
__device__ bf16  g_yl[(size_t)MROWS*CDIM];
__device__ bf16  g_hh[(size_t)MROWS*2*CDIM];
__device__ bf16  g_hl[(size_t)MROWS*2*CDIM];
__device__ bf16  g_wqh[(size_t)NLAYER*3*CDIM*CDIM];   // W^T [N][K] hi/lo
__device__ bf16  g_wql[(size_t)NLAYER*3*CDIM*CDIM];
__device__ bf16  g_w1h[(size_t)NLAYER*2*CDIM*CDIM];
__device__ bf16  g_w1l[(size_t)NLAYER*2*CDIM*CDIM];
__device__ bf16  g_w2h[(size_t)NLAYER*2*CDIM*CDIM];
__device__ bf16  g_w2l[(size_t)NLAYER*2*CDIM*CDIM];

// ---------------- helpers --------------------------------------------------
__device__ __forceinline__ uint32_t s2u(const void* p){
    uint32_t a;
    asm("{ .reg .u64 t; cvta.to.shared.u64 t, %1; cvt.u32.u64 %0, t; }" : "=r"(a) : "l"(p));
    return a;
}
__device__ __forceinline__ void cpa16(uint32_t s, const void* g){
    asm volatile("cp.async.cg.shared.global [%0], [%1], 16;" :: "r"(s), "l"(g));
}
__device__ __forceinline__ void ldmx4(uint32_t* r, uint32_t addr){
    asm volatile("ldmatrix.sync.aligned.m8n8.x4.shared.b16 {%0,%1,%2,%3}, [%4];"
        : "=r"(r[0]), "=r"(r[1]), "=r"(r[2]), "=r"(r[3]) : "r"(addr));
}
__device__ __forceinline__ void mma16816(float* c, const uint32_t* a, const uint32_t* b){
    asm volatile("mma.sync.aligned.m16n8k16.row.col.f32.bf16.bf16.f32 "
        "{%0,%1,%2,%3}, {%4,%5,%6,%7}, {%8,%9}, {%0,%1,%2,%3};"
        : "+f"(c[0]), "+f"(c[1]), "+f"(c[2]), "+f"(c[3])
        : "r"(a[0]), "r"(a[1]), "r"(a[2]), "r"(a[3]), "r"(b[0]), "r"(b[1]));
}
__device__ __forceinline__ void split2(float v0, float v1, uint32_t& hp, uint32_t& lp){
    bf16 h0=__float2bfloat16(v0), h1=__float2bfloat16(v1);
    bf16 l0=__float2bfloat16(v0-__bfloat162float(h0));
    bf16 l1=__float2bfloat16(v1-__bfloat162float(h1));
    hp = (uint32_t)__bfloat16_as_ushort(h0) | ((uint32_t)__bfloat16_as_ushort(h1)<<16);
    lp = (uint32_t)__bfloat16_as_ushort(l0) | ((uint32_t)__bfloat16_as_ushort(l1)<<16);
}

// smem: 2 stages x (Ah|Al|Bh|Bl), each half = 128 rows x 40 bf16 (32 data + pad)
// row stride 80B -> ldmatrix 8-row access is bank-conflict-free.
#define ROWB   80
#define HALF_B 10240
#define STG_B  40960
#define SMEMSZ (2*STG_B)

// ---------------- stage loader ----------------------------------------------
template<int MODE>
__device__ __forceinline__ void load_stage(char* smc, uint32_t sb, int s, int k0, int t,
    const float* Afp, const bf16* Ah, const bf16* Al, const bf16* Bh, const bf16* Bl,
    int rA0, int c0)
{
    constexpr int LDA = (MODE==2)?2048:((MODE==4)?1024:512);
    const uint32_t st = sb + (uint32_t)s*STG_B;
    char* sd = smc + s*STG_B;
    if (MODE==0){
        // A: fp32 -> split in regs -> STS (hi half + lo half)
#pragma unroll
        for (int i=0;i<2;i++){
            int f=t+i*256, row=f>>2, kq=f&3;
            const float* src = Afp + (size_t)(rA0+row)*512 + k0 + kq*8;
            float4 u0=*(const float4*)src, u1=*(const float4*)(src+4);
            float vv[8]={u0.x,u0.y,u0.z,u0.w,u1.x,u1.y,u1.z,u1.w};
            __align__(16) bf16 hh[8]; __align__(16) bf16 ll[8];
#pragma unroll
            for (int j2=0;j2<8;j2++){
                hh[j2]=__float2bfloat16(vv[j2]);
                ll[j2]=__float2bfloat16(vv[j2]-__bfloat162float(hh[j2]));
            }
            char* d = sd + row*ROWB + kq*16;
            *(uint4*)d            = *(uint4*)hh;
            *(uint4*)(d + HALF_B) = *(uint4*)ll;
        }
        // B: pre-split weights via cp.async
#pragma unroll
        for (int i=0;i<4;i++){
            int f=t+i*256, hf=f>>9, idx=f&511, row=idx>>2, kq=idx&3;
            const bf16* src = (hf? Bl:Bh) + (size_t)(c0+row)*512 + k0 + kq*8;
            cpa16(st + 2*HALF_B + hf*HALF_B + row*ROWB + kq*16, src);
        }
    } else {
#pragma unroll
        for (int i=0;i<8;i++){
            int f=t+i*256, hf=f>>9, idx=f&511, row=idx>>2, kq=idx&3;
            const bf16* base = (hf==0)?Ah:((hf==1)?Al:((hf==2)?Bh:Bl));
            int r = (hf<2)?(rA0+row):(c0+row);
            cpa16(st + hf*HALF_B + row*ROWB + kq*16, base + (size_t)r*LDA + k0 + kq*8);
        }
    }
    asm volatile("cp.async.commit_group;" ::: "memory");
}

// ---------------- per-stage compute (2 k-steps of 16) -----------------------
__device__ __forceinline__ void compute_stage(uint32_t st, int wm0, int wn0, int lane,
                                              float acc[4][4][4])
{
#pragma unroll
    for (int kk=0; kk<32; kk+=16){
        uint32_t ah[4][4], al[4][4], bh[4][2], bl[4][2];
        const uint32_t acol = (uint32_t)(kk + (lane>>4)*8)*2;
#pragma unroll
        for (int i=0;i<4;i++){
            uint32_t ra = st + (uint32_t)(wm0 + i*16 + (lane&15))*ROWB + acol;
            ldmx4(ah[i], ra);
            ldmx4(al[i], ra + HALF_B);
        }
        const uint32_t bcol = (uint32_t)(kk + ((lane>>3)&1)*8)*2;
#pragma unroll
        for (int p=0;p<2;p++){
            uint32_t rb_ = st + 2*HALF_B
                         + (uint32_t)(wn0 + p*16 + (lane&7) + (lane>>4)*8)*ROWB + bcol;
            uint32_t r4[4];
            ldmx4(r4, rb_);
            bh[p*2][0]=r4[0]; bh[p*2][1]=r4[1]; bh[p*2+1][0]=r4[2]; bh[p*2+1][1]=r4[3];
            ldmx4(r4, rb_ + HALF_B);
            bl[p*2][0]=r4[0]; bl[p*2][1]=r4[1]; bl[p*2+1][0]=r4[2]; bl[p*2+1][1]=r4[3];
        }
#pragma unroll
        for (int i=0;i<4;i++)
#pragma unroll
            for (int j=0;j<4;j++){
                mma16816(acc[i][j], ah[i], bh[j]);
                mma16816(acc[i][j], ah[i], bl[j]);
                mma16816(acc[i][j], al[i], bh[j]);
            }
    }
}

// ---------------- GEMM kernel ------------------------------------------------
// MODE 0: qkv   A=fp32 src (split on fly), B=WqT; epi: +bias -> split Q/K/V^T
// MODE 1: score A=Q(split),  B=K(split per-batch); epi: *scale -> S fp32 (tile skip)
// MODE 2: attnv A=S(split),  B=V^T(split per-batch); epi -> Out fp32 (k-trunc)
// MODE 3: fc1   A=y(split),  B=W1T; epi: +bias, gelu -> split h
// MODE 4: fc2   A=h(split),  B=W2T; epi: Out += v+bias
template<int MODE>
__global__ __launch_bounds__(256,1)
void gemm_mma(const float* __restrict__ Afp, const bf16* __restrict__ Bwh,
              const bf16* __restrict__ Bwl, const float* __restrict__ bias,
              float* __restrict__ Out)
{
    const int t=threadIdx.x, lane=t&31, warp=t>>5;
    const int wm0=(warp&1)*64, wn0=(warp>>1)*32;
    const int bx=blockIdx.x, by=blockIdx.y;
    const int rb=by&15, b=by>>4;
    if (MODE==1){ if (rb<8){ if (bx>=8) return; } else { if (bx>rb) return; } }
    const int c0=bx*128;
    const int rA0=(MODE==2)?(rb*128):(by*128);
    int nT;
    if (MODE==2)      nT = ((rb<8)?1024:((rb+1)*128)) >> 5;
    else if (MODE==4) nT = 32;
    else              nT = 16;

    const bf16 *Ah=nullptr,*Al=nullptr,*Bh=Bwh,*Bl=Bwl;
    if (MODE==1){ Ah=g_qh; Al=g_ql;
                  Bh=g_kh+(size_t)b*NTOK*CDIM; Bl=g_kl+(size_t)b*NTOK*CDIM; }
    if (MODE==2){ Ah=g_sh+(size_t)b*NN; Al=g_sl+(size_t)b*NN;
                  Bh=g_vth+(size_t)b*CDIM*NTOK; Bl=g_vtl+(size_t)b*CDIM*NTOK; }
    if (MODE==3){ Ah=g_yh; Al=g_yl; }
    if (MODE==4){ Ah=g_hh; Al=g_hl; }

    extern __shared__ char smc[];
    const uint32_t sb = s2u(smc);

    float acc[4][4][4];
#pragma unroll
    for (int i=0;i<4;i++)
#pragma unroll
        for (int j=0;j<4;j++)
#pragma unroll
            for (int q=0;q<4;q++) acc[i][j][q]=0.f;

    load_stage<MODE>(smc, sb, 0, 0,  t, Afp, Ah, Al, Bh, Bl, rA0, c0);
    load_stage<MODE>(smc, sb, 1, 32, t, Afp, Ah, Al, Bh, Bl, rA0, c0);
    for (int ti=0; ti<nT; ti++){
        if (ti<nT-1) asm volatile("cp.async.wait_group 1;" ::: "memory");
        else         asm volatile("cp.async.wait_group 0;" ::: "memory");
        __syncthreads();
        compute_stage(sb + (uint32_t)(ti&1)*STG_B, wm0, wn0, lane, acc);
        __syncthreads();
        if (ti+2<nT)
            load_stage<MODE>(smc, sb, ti&1, (ti+2)*32, t, Afp, Ah, Al, Bh, Bl, rA0, c0);
    }

    // ---------------- epilogue ----------------
    const int lr=lane>>2, lc=(lane&3)*2;
#pragma unroll
    for (int i=0;i<4;i++){
#pragma unroll
        for (int h=0;h<2;h++){
            const int r  = wm0 + i*16 + lr + h*8;
            const int gr = by*128 + r;
#pragma unroll
            for (int j=0;j<4;j++){
                const int c = c0 + wn0 + j*8 + lc;
                float v0=acc[i][j][h*2], v1=acc[i][j][h*2+1];
                if (MODE==0){
                    v0 += bias[c]; v1 += bias[c+1];
                    if (c<1024){
                        uint32_t ph, pl; split2(v0,v1,ph,pl);
                        if (c<512){
                            *(uint32_t*)&g_qh[(size_t)gr*512+c]=ph;
                            *(uint32_t*)&g_ql[(size_t)gr*512+c]=pl;
                        } else {
                            *(uint32_t*)&g_kh[(size_t)gr*512+(c-512)]=ph;
                            *(uint32_t*)&g_kl[(size_t)gr*512+(c-512)]=pl;
                        }
                    } else {
                        int cv=c-1024, bb=gr>>11, n=gr&2047;
                        bf16 h0=__float2bfloat16(v0);
                        bf16 l0=__float2bfloat16(v0-__bfloat162float(h0));
                        bf16 h1=__float2bfloat16(v1);
                        bf16 l1=__float2bfloat16(v1-__bfloat162float(h1));
                        size_t o0=((size_t)bb*512+cv)*2048+n;
                        size_t o1=((size_t)bb*512+cv+1)*2048+n;
                        g_vth[o0]=h0; g_vtl[o0]=l0;
                        g_vth[o1]=h1; g_vtl[o1]=l1;
                    }
                } else if (MODE==1){
                    const int orow = rb*128 + r;
                    float2 vv = { v0*0.044194173824159216f, v1*0.044194173824159216f };
                    *(float2*)&g_S[(size_t)b*NN + (size_t)orow*2048 + c] = vv;
                } else if (MODE==2){
                    float2 vv = { v0, v1 };
                    *(float2*)&Out[(size_t)gr*512 + c] = vv;
                } else if (MODE==3){
                    v0+=bias[c]; v1+=bias[c+1];
                    v0 = 0.5f*v0*(1.f+erff(v0*0.70710678118654752f));
                    v1 = 0.5f*v1*(1.f+erff(v1*0.70710678118654752f));
                    uint32_t ph,pl; split2(v0,v1,ph,pl);
                    *(uint32_t*)&g_hh[(size_t)gr*1024+c]=ph;
                    *(uint32_t*)&g_hl[(size_t)gr*1024+c]=pl;
                } else {
                    float2* p=(float2*)&Out[(size_t)gr*512+c];
                    float2 o=*p;
                    o.x += v0 + bias[c];
                    o.y += v1 + bias[c+1];
                    *p=o;
                }
            }
        }
    }
}

// ---------------- masked softmax: fp32 S row -> split-bf16 ------------------
__global__ __launch_bounds__(256)
void softmax_k()
{
    const int row = blockIdx.x;
    const int b = row >> 11, i = row & (NTOK-1);
    const int limit = (i < 1024) ? 1024 : (i+1);
    const int kmax  = (i < 1024) ? 1024 : (((i>>7)+1)<<7);
    const float* p = g_S + (size_t)b*NN + (size_t)i*NTOK;
    bf16* ph = g_sh + (size_t)b*NN + (size_t)i*NTOK;
    bf16* pl = g_sl + (size_t)b*NN + (size_t)i*NTOK;
    const int t = threadIdx.x;
    float vals[8]; float m = -1e30f;
#pragma unroll
    for (int j=0;j<8;j++){ int idx=t+j*256; vals[j]=(idx<limit)?p[idx]:-1e30f; m=fmaxf(m,vals[j]); }
    __shared__ float red[256];
    red[t]=m; __syncthreads();
    for (int s=128;s>0;s>>=1){ if(t<s) red[t]=fmaxf(red[t],red[t+s]); __syncthreads(); }
    m = red[0]; __syncthreads();
    float sum=0.f;
#pragma unroll
    for (int j=0;j<8;j++){ int idx=t+j*256; if(idx<limit){ vals[j]=expf(vals[j]-m); sum+=vals[j]; } else vals[j]=0.f; }
    red[t]=sum; __syncthreads();
    for (int s=128;s>0;s>>=1){ if(t<s) red[t]+=red[t+s]; __syncthreads(); }
    const float inv = 1.f/red[0];
#pragma unroll
    for (int j=0;j<8;j++){
        int idx=t+j*256;
        if (idx<kmax){
            float v = vals[j]*inv;
            bf16 h=__float2bfloat16(v);
            bf16 l=__float2bfloat16(v-__bfloat162float(h));
            ph[idx]=h; pl[idx]=l;
        }
    }
}

// ---------------- LayerNorm -> split-bf16 y ---------------------------------
__global__ __launch_bounds__(256)
void layernorm_k(const float* __restrict__ X, const float* __restrict__ g,
                 const float* __restrict__ bta)
{
    const int row = blockIdx.x;
    const float* x = X + (size_t)row*CDIM;
    const int t = threadIdx.x;
    float v0=x[t], v1=x[t+256];
    __shared__ float red[256];
    red[t]=v0+v1; __syncthreads();
    for (int s=128;s>0;s>>=1){ if(t<s) red[t]+=red[t+s]; __syncthreads(); }
    const float mu = red[0]*(1.f/CDIM); __syncthreads();
    float d0=v0-mu, d1=v1-mu;
    red[t]=d0*d0+d1*d1; __syncthreads();
    for (int s=128;s>0;s>>=1){ if(t<s) red[t]+=red[t+s]; __syncthreads(); }
    const float inv = rsqrtf(red[0]*(1.f/CDIM)+1e-5f);
    float y0 = d0*inv*g[t]+bta[t];
    float y1 = d1*inv*g[t+256]+bta[t+256];
    bf16 h=__float2bfloat16(y0);
    g_yh[(size_t)row*CDIM+t]=h;
    g_yl[(size_t)row*CDIM+t]=__float2bfloat16(y0-__bfloat162float(h));
    h=__float2bfloat16(y1);
    g_yh[(size_t)row*CDIM+t+256]=h;
    g_yl[(size_t)row*CDIM+t+256]=__float2bfloat16(y1-__bfloat162float(h));
}

// ---------------- weight transpose + split: W[K][N] -> T[N][K] hi/lo --------
__global__ void wsplit_t(const float* __restrict__ W, bf16* __restrict__ Th,
                         bf16* __restrict__ Tl, int K, int N)
{
    __shared__ float tile[32][33];
    const int k0 = blockIdx.y*32, n0 = blockIdx.x*32;
    const int tx = threadIdx.x, ty = threadIdx.y;   // 32x8
#pragma unroll
    for (int i=0;i<32;i+=8)
        tile[ty+i][tx] = W[(size_t)(k0+ty+i)*N + n0+tx];
    __syncthreads();
#pragma unroll
    for (int i=0;i<32;i+=8){
        float v = tile[tx][ty+i];
        bf16 h=__float2bfloat16(v);
        Th[(size_t)(n0+ty+i)*K + k0+tx] = h;
        Tl[(size_t)(n0+ty+i)*K + k0+tx] = __float2bfloat16(v-__bfloat162float(h));
    }
}

// ---------------------------------------------------------------------------
extern "C" void kernel_launch(void* const* d_in, const int* in_sizes, int n_in,
                              void* d_out, int out_size)
{
    const float* x_in  = (const float*)d_in[0];
    const float* qkv_w = (const float*)d_in[1];
    const float* qkv_b = (const float*)d_in[2];
    const float* ln_g  = (const float*)d_in[3];
    const float* ln_b  = (const float*)d_in[4];
    const float* fc1_w = (const float*)d_in[5];
    const float* fc1_b = (const float*)d_in[6];
    const float* fc2_w = (const float*)d_in[7];
    const float* fc2_b = (const float*)d_in[8];
    float* out = (float*)d_out;

    bf16 *wqh,*wql,*w1h,*w1l,*w2h,*w2l;
    cudaGetSymbolAddress((void**)&wqh, g_wqh);
    cudaGetSymbolAddress((void**)&wql, g_wql);
    cudaGetSymbolAddress((void**)&w1h, g_w1h);
    cudaGetSymbolAddress((void**)&w1l, g_w1l);
    cudaGetSymbolAddress((void**)&w2h, g_w2h);
    cudaGetSymbolAddress((void**)&w2l, g_w2l);

    cudaFuncSetAttribute(gemm_mma<0>, cudaFuncAttributeMaxDynamicSharedMemorySize, SMEMSZ);
    cudaFuncSetAttribute(gemm_mma<1>, cudaFuncAttributeMaxDynamicSharedMemorySize, SMEMSZ);
    cudaFuncSetAttribute(gemm_mma<2>, cudaFuncAttributeMaxDynamicSharedMemorySize, SMEMSZ);
    cudaFuncSetAttribute(gemm_mma<3>, cudaFuncAttributeMaxDynamicSharedMemorySize, SMEMSZ);
    cudaFuncSetAttribute(gemm_mma<4>, cudaFuncAttributeMaxDynamicSharedMemorySize, SMEMSZ);

    const dim3 thr(256);
    const dim3 tb(32,8);

    // weight prep (transposed split copies)
    for (int l=0;l<NLAYER;l++){
        wsplit_t<<<dim3(48,16), tb>>>(qkv_w + (size_t)l*CDIM*3*CDIM,
                                      wqh + (size_t)l*3*CDIM*CDIM,
                                      wql + (size_t)l*3*CDIM*CDIM, 512, 1536);
        wsplit_t<<<dim3(32,16), tb>>>(fc1_w + (size_t)l*CDIM*2*CDIM,
                                      w1h + (size_t)l*2*CDIM*CDIM,
                                      w1l + (size_t)l*2*CDIM*CDIM, 512, 1024);
        wsplit_t<<<dim3(16,32), tb>>>(fc2_w + (size_t)l*2*CDIM*CDIM,
                                      w2h + (size_t)l*2*CDIM*CDIM,
                                      w2l + (size_t)l*2*CDIM*CDIM, 1024, 512);
    }

    for (int l=0;l<NLAYER;l++){
        const float* src = (l==0) ? x_in : out;
        gemm_mma<0><<<dim3(12,128), thr, SMEMSZ>>>(src,
            wqh + (size_t)l*3*CDIM*CDIM, wql + (size_t)l*3*CDIM*CDIM,
            qkv_b + (size_t)l*3*CDIM, nullptr);
        gemm_mma<1><<<dim3(16,128), thr, SMEMSZ>>>(nullptr, nullptr, nullptr, nullptr, nullptr);
        softmax_k<<<MROWS, thr>>>();
        gemm_mma<2><<<dim3(4,128), thr, SMEMSZ>>>(nullptr, nullptr, nullptr, nullptr, out);
        layernorm_k<<<MROWS, thr>>>(out, ln_g + (size_t)l*CDIM, ln_b + (size_t)l*CDIM);
        gemm_mma<3><<<dim3(8,128), thr, SMEMSZ>>>(nullptr,
            w1h + (size_t)l*2*CDIM*CDIM, w1l + (size_t)l*2*CDIM*CDIM,
            fc1_b + (size_t)l*2*CDIM, nullptr);
        gemm_mma<4><<<dim3(4,128), thr, SMEMSZ>>>(nullptr,
            w2h + (size_t)l*2*CDIM*CDIM, w2l + (size_t)l*2*CDIM*CDIM,
            fc2_b + (size_t)l*CDIM, out);
    }
}

// round 11
// speedup vs baseline: 2.1610x; 1.0259x over previous
#include <cuda_runtime.h>
#include <cuda_bf16.h>
#include <math.h>
#include <stdint.h>

typedef __nv_bfloat16 bf16;

#define CDIM   512
#define NTOK   2048
#define BATCH  8
#define NLAYER 5
#define MROWS  16384
#define NN     ((size_t)NTOK*NTOK)

// ---------------- scratch (device globals; allocation-free rule) -----------
__device__ float g_S [(size_t)BATCH*NN];
__device__ bf16  g_sh[(size_t)BATCH*NN];
__device__ bf16  g_sl[(size_t)BATCH*NN];
__device__ bf16  g_qh[(size_t)MROWS*CDIM];
__device__ bf16  g_ql[(size_t)MROWS*CDIM];
__device__ bf16  g_kh[(size_t)MROWS*CDIM];
__device__ bf16  g_kl[(size_t)MROWS*CDIM];
__device__ bf16  g_vth[(size_t)MROWS*CDIM];   // V^T: [b][c][n]
__device__ bf16  g_vtl[(size_t)MROWS*CDIM];
__device__ bf16  g_yh[(size_t)MROWS*CDIM];
__device__ bf16  g_yl[(size_t)MROWS*CDIM];
__device__ bf16  g_hh[(size_t)MROWS*2*CDIM];
__device__ bf16  g_hl[(size_t)MROWS*2*CDIM];
__device__ bf16  g_wqh[(size_t)NLAYER*3*CDIM*CDIM];   // W^T [N][K] hi/lo
__device__ bf16  g_wql[(size_t)NLAYER*3*CDIM*CDIM];
__device__ bf16  g_w1h[(size_t)NLAYER*2*CDIM*CDIM];
__device__ bf16  g_w1l[(size_t)NLAYER*2*CDIM*CDIM];
__device__ bf16  g_w2h[(size_t)NLAYER*2*CDIM*CDIM];
__device__ bf16  g_w2l[(size_t)NLAYER*2*CDIM*CDIM];

// ---------------- helpers --------------------------------------------------
__device__ __forceinline__ uint32_t s2u(const void* p){
    uint32_t a;
    asm("{ .reg .u64 t; cvta.to.shared.u64 t, %1; cvt.u32.u64 %0, t; }" : "=r"(a) : "l"(p));
    return a;
}
__device__ __forceinline__ void cpa16(uint32_t s, const void* g){
    asm volatile("cp.async.cg.shared.global [%0], [%1], 16;" :: "r"(s), "l"(g));
}
__device__ __forceinline__ void ldmx4(uint32_t* r, uint32_t addr){
    asm volatile("ldmatrix.sync.aligned.m8n8.x4.shared.b16 {%0,%1,%2,%3}, [%4];"
        : "=r"(r[0]), "=r"(r[1]), "=r"(r[2]), "=r"(r[3]) : "r"(addr));
}
__device__ __forceinline__ void mma16816(float* c, const uint32_t* a, const uint32_t* b){
    asm volatile("mma.sync.aligned.m16n8k16.row.col.f32.bf16.bf16.f32 "
        "{%0,%1,%2,%3}, {%4,%5,%6,%7}, {%8,%9}, {%0,%1,%2,%3};"
        : "+f"(c[0]), "+f"(c[1]), "+f"(c[2]), "+f"(c[3])
        : "r"(a[0]), "r"(a[1]), "r"(a[2]), "r"(a[3]), "r"(b[0]), "r"(b[1]));
}
__device__ __forceinline__ void split2(float v0, float v1, uint32_t& hp, uint32_t& lp){
    bf16 h0=__float2bfloat16(v0), h1=__float2bfloat16(v1);
    bf16 l0=__float2bfloat16(v0-__bfloat162float(h0));
    bf16 l1=__float2bfloat16(v1-__bfloat162float(h1));
    hp = (uint32_t)__bfloat16_as_ushort(h0) | ((uint32_t)__bfloat16_as_ushort(h1)<<16);
    lp = (uint32_t)__bfloat16_as_ushort(l0) | ((uint32_t)__bfloat16_as_ushort(l1)<<16);
}

// smem: 4 stages x (Ah|Al|Bh|Bl), each half = 128 rows x 40 bf16 (32 data + pad)
// row stride 80B -> ldmatrix 8-row access is bank-conflict-free.
#define ROWB   80
#define HALF_B 10240
#define STG_B  40960
#define NSTG   4
#define SMEMSZ (NSTG*STG_B)

// ---------------- stage loader ----------------------------------------------
template<int MODE>
__device__ __forceinline__ void load_stage(char* smc, uint32_t sb, int s, int k0, int t,
    const float* Afp, const bf16* Ah, const bf16* Al, const bf16* Bh, const bf16* Bl,
    int rA0, int c0)
{
    constexpr int LDA = (MODE==2)?2048:((MODE==4)?1024:512);
    const uint32_t st = sb + (uint32_t)s*STG_B;
    char* sd = smc + s*STG_B;
    if (MODE==0){
        // A: fp32 -> split in regs -> STS (hi half + lo half)
#pragma unroll
        for (int i=0;i<2;i++){
            int f=t+i*256, row=f>>2, kq=f&3;
            const float* src = Afp + (size_t)(rA0+row)*512 + k0 + kq*8;
            float4 u0=*(const float4*)src, u1=*(const float4*)(src+4);
            float vv[8]={u0.x,u0.y,u0.z,u0.w,u1.x,u1.y,u1.z,u1.w};
            __align__(16) bf16 hh[8]; __align__(16) bf16 ll[8];
#pragma unroll
            for (int j2=0;j2<8;j2++){
                hh[j2]=__float2bfloat16(vv[j2]);
                ll[j2]=__float2bfloat16(vv[j2]-__bfloat162float(hh[j2]));
            }
            char* d = sd + row*ROWB + kq*16;
            *(uint4*)d            = *(uint4*)hh;
            *(uint4*)(d + HALF_B) = *(uint4*)ll;
        }
        // B: pre-split weights via cp.async
#pragma unroll
        for (int i=0;i<4;i++){
            int f=t+i*256, hf=f>>9, idx=f&511, row=idx>>2, kq=idx&3;
            const bf16* src = (hf? Bl:Bh) + (size_t)(c0+row)*512 + k0 + kq*8;
            cpa16(st + 2*HALF_B + hf*HALF_B + row*ROWB + kq*16, src);
        }
    } else {
#pragma unroll
        for (int i=0;i<8;i++){
            int f=t+i*256, hf=f>>9, idx=f&511, row=idx>>2, kq=idx&3;
            const bf16* base = (hf==0)?Ah:((hf==1)?Al:((hf==2)?Bh:Bl));
            int r = (hf<2)?(rA0+row):(c0+row);
            cpa16(st + hf*HALF_B + row*ROWB + kq*16, base + (size_t)r*LDA + k0 + kq*8);
        }
    }
    asm volatile("cp.async.commit_group;" ::: "memory");
}

// ---------------- per-stage compute (2 k-steps of 16) -----------------------
__device__ __forceinline__ void compute_stage(uint32_t st, int wm0, int wn0, int lane,
                                              float acc[4][4][4])
{
#pragma unroll
    for (int kk=0; kk<32; kk+=16){
        uint32_t ah[4][4], al[4][4], bh[4][2], bl[4][2];
        const uint32_t acol = (uint32_t)(kk + (lane>>4)*8)*2;
#pragma unroll
        for (int i=0;i<4;i++){
            uint32_t ra = st + (uint32_t)(wm0 + i*16 + (lane&15))*ROWB + acol;
            ldmx4(ah[i], ra);
            ldmx4(al[i], ra + HALF_B);
        }
        const uint32_t bcol = (uint32_t)(kk + ((lane>>3)&1)*8)*2;
#pragma unroll
        for (int p=0;p<2;p++){
            uint32_t rb_ = st + 2*HALF_B
                         + (uint32_t)(wn0 + p*16 + (lane&7) + (lane>>4)*8)*ROWB + bcol;
            uint32_t r4[4];
            ldmx4(r4, rb_);
            bh[p*2][0]=r4[0]; bh[p*2][1]=r4[1]; bh[p*2+1][0]=r4[2]; bh[p*2+1][1]=r4[3];
            ldmx4(r4, rb_ + HALF_B);
            bl[p*2][0]=r4[0]; bl[p*2][1]=r4[1]; bl[p*2+1][0]=r4[2]; bl[p*2+1][1]=r4[3];
        }
#pragma unroll
        for (int i=0;i<4;i++)
#pragma unroll
            for (int j=0;j<4;j++){
                mma16816(acc[i][j], ah[i], bh[j]);
                mma16816(acc[i][j], ah[i], bl[j]);
                mma16816(acc[i][j], al[i], bh[j]);
            }
    }
}

// ---------------- GEMM kernel ------------------------------------------------
// MODE 0: qkv   A=fp32 src (split on fly), B=WqT; epi: +bias -> split Q/K/V^T
// MODE 1: score A=Q(split),  B=K(split per-batch); epi: *scale -> S fp32 (tile skip)
// MODE 2: attnv A=S(split),  B=V^T(split per-batch); epi -> Out fp32 (k-trunc)
// MODE 3: fc1   A=y(split),  B=W1T; epi: +bias, gelu -> split h
// MODE 4: fc2   A=h(split),  B=W2T; epi: Out += v+bias
template<int MODE>
__global__ __launch_bounds__(256,1)
void gemm_mma(const float* __restrict__ Afp, const bf16* __restrict__ Bwh,
              const bf16* __restrict__ Bwl, const float* __restrict__ bias,
              float* __restrict__ Out)
{
    const int t=threadIdx.x, lane=t&31, warp=t>>5;
    const int wm0=(warp&1)*64, wn0=(warp>>1)*32;
    const int bx=blockIdx.x, by=blockIdx.y;
    const int rb=by&15, b=by>>4;
    if (MODE==1){ if (rb<8){ if (bx>=8) return; } else { if (bx>rb) return; } }
    const int c0=bx*128;
    const int rA0=(MODE==2)?(rb*128):(by*128);
    int nT;
    if (MODE==2)      nT = ((rb<8)?1024:((rb+1)*128)) >> 5;
    else if (MODE==4) nT = 32;
    else              nT = 16;

    const bf16 *Ah=nullptr,*Al=nullptr,*Bh=Bwh,*Bl=Bwl;
    if (MODE==1){ Ah=g_qh; Al=g_ql;
                  Bh=g_kh+(size_t)b*NTOK*CDIM; Bl=g_kl+(size_t)b*NTOK*CDIM; }
    if (MODE==2){ Ah=g_sh+(size_t)b*NN; Al=g_sl+(size_t)b*NN;
                  Bh=g_vth+(size_t)b*CDIM*NTOK; Bl=g_vtl+(size_t)b*CDIM*NTOK; }
    if (MODE==3){ Ah=g_yh; Al=g_yl; }
    if (MODE==4){ Ah=g_hh; Al=g_hl; }

    extern __shared__ char smc[];
    const uint32_t sb = s2u(smc);

    float acc[4][4][4];
#pragma unroll
    for (int i=0;i<4;i++)
#pragma unroll
        for (int j=0;j<4;j++)
#pragma unroll
            for (int q=0;q<4;q++) acc[i][j][q]=0.f;

    // prologue: prefetch 3 stages (nT >= 16 always)
    load_stage<MODE>(smc, sb, 0, 0,  t, Afp, Ah, Al, Bh, Bl, rA0, c0);
    load_stage<MODE>(smc, sb, 1, 32, t, Afp, Ah, Al, Bh, Bl, rA0, c0);
    load_stage<MODE>(smc, sb, 2, 64, t, Afp, Ah, Al, Bh, Bl, rA0, c0);
    for (int ti=0; ti<nT; ti++){
        const int rem = nT - 1 - ti;
        if (rem >= 2)      asm volatile("cp.async.wait_group 2;" ::: "memory");
        else if (rem == 1) asm volatile("cp.async.wait_group 1;" ::: "memory");
        else               asm volatile("cp.async.wait_group 0;" ::: "memory");
        __syncthreads();   // stage ti visible to all; slot (ti+3)&3 free (consumed at ti-1)
        if (ti+3 < nT)
            load_stage<MODE>(smc, sb, (ti+3)&3, (ti+3)*32, t, Afp, Ah, Al, Bh, Bl, rA0, c0);
        compute_stage(sb + (uint32_t)(ti&3)*STG_B, wm0, wn0, lane, acc);
    }

    // ---------------- epilogue ----------------
    const int lr=lane>>2, lc=(lane&3)*2;
#pragma unroll
    for (int i=0;i<4;i++){
#pragma unroll
        for (int h=0;h<2;h++){
            const int r  = wm0 + i*16 + lr + h*8;
            const int gr = by*128 + r;
#pragma unroll
            for (int j=0;j<4;j++){
                const int c = c0 + wn0 + j*8 + lc;
                float v0=acc[i][j][h*2], v1=acc[i][j][h*2+1];
                if (MODE==0){
                    v0 += bias[c]; v1 += bias[c+1];
                    if (c<1024){
                        uint32_t ph, pl; split2(v0,v1,ph,pl);
                        if (c<512){
                            *(uint32_t*)&g_qh[(size_t)gr*512+c]=ph;
                            *(uint32_t*)&g_ql[(size_t)gr*512+c]=pl;
                        } else {
                            *(uint32_t*)&g_kh[(size_t)gr*512+(c-512)]=ph;
                            *(uint32_t*)&g_kl[(size_t)gr*512+(c-512)]=pl;
                        }
                    } else {
                        int cv=c-1024, bb=gr>>11, n=gr&2047;
                        bf16 h0=__float2bfloat16(v0);
                        bf16 l0=__float2bfloat16(v0-__bfloat162float(h0));
                        bf16 h1=__float2bfloat16(v1);
                        bf16 l1=__float2bfloat16(v1-__bfloat162float(h1));
                        size_t o0=((size_t)bb*512+cv)*2048+n;
                        size_t o1=((size_t)bb*512+cv+1)*2048+n;
                        g_vth[o0]=h0; g_vtl[o0]=l0;
                        g_vth[o1]=h1; g_vtl[o1]=l1;
                    }
                } else if (MODE==1){
                    const int orow = rb*128 + r;
                    float2 vv = { v0*0.044194173824159216f, v1*0.044194173824159216f };
                    *(float2*)&g_S[(size_t)b*NN + (size_t)orow*2048 + c] = vv;
                } else if (MODE==2){
                    float2 vv = { v0, v1 };
                    *(float2*)&Out[(size_t)gr*512 + c] = vv;
                } else if (MODE==3){
                    v0+=bias[c]; v1+=bias[c+1];
                    v0 = 0.5f*v0*(1.f+erff(v0*0.70710678118654752f));
                    v1 = 0.5f*v1*(1.f+erff(v1*0.70710678118654752f));
                    uint32_t ph,pl; split2(v0,v1,ph,pl);
                    *(uint32_t*)&g_hh[(size_t)gr*1024+c]=ph;
                    *(uint32_t*)&g_hl[(size_t)gr*1024+c]=pl;
                } else {
                    float2* p=(float2*)&Out[(size_t)gr*512+c];
                    float2 o=*p;
                    o.x += v0 + bias[c];
                    o.y += v1 + bias[c+1];
                    *p=o;
                }
            }
        }
    }
}

// ---------------- masked softmax: fp32 S row -> split-bf16 ------------------
__global__ __launch_bounds__(256)
void softmax_k()
{
    const int row = blockIdx.x;
    const int b = row >> 11, i = row & (NTOK-1);
    const int limit = (i < 1024) ? 1024 : (i+1);
    const int kmax  = (i < 1024) ? 1024 : (((i>>7)+1)<<7);
    const float* p = g_S + (size_t)b*NN + (size_t)i*NTOK;
    bf16* ph = g_sh + (size_t)b*NN + (size_t)i*NTOK;
    bf16* pl = g_sl + (size_t)b*NN + (size_t)i*NTOK;
    const int t = threadIdx.x;
    float vals[8]; float m = -1e30f;
#pragma unroll
    for (int j=0;j<8;j++){ int idx=t+j*256; vals[j]=(idx<limit)?p[idx]:-1e30f; m=fmaxf(m,vals[j]); }
    __shared__ float red[256];
    red[t]=m; __syncthreads();
    for (int s=128;s>0;s>>=1){ if(t<s) red[t]=fmaxf(red[t],red[t+s]); __syncthreads(); }
    m = red[0]; __syncthreads();
    float sum=0.f;
#pragma unroll
    for (int j=0;j<8;j++){ int idx=t+j*256; if(idx<limit){ vals[j]=expf(vals[j]-m); sum+=vals[j]; } else vals[j]=0.f; }
    red[t]=sum; __syncthreads();
    for (int s=128;s>0;s>>=1){ if(t<s) red[t]+=red[t+s]; __syncthreads(); }
    const float inv = 1.f/red[0];
#pragma unroll
    for (int j=0;j<8;j++){
        int idx=t+j*256;
        if (idx<kmax){
            float v = vals[j]*inv;
            bf16 h=__float2bfloat16(v);
            bf16 l=__float2bfloat16(v-__bfloat162float(h));
            ph[idx]=h; pl[idx]=l;
        }
    }
}

// ---------------- LayerNorm -> split-bf16 y ---------------------------------
__global__ __launch_bounds__(256)
void layernorm_k(const float* __restrict__ X, const float* __restrict__ g,
                 const float* __restrict__ bta)
{
    const int row = blockIdx.x;
    const float* x = X + (size_t)row*CDIM;
    const int t = threadIdx.x;
    float v0=x[t], v1=x[t+256];
    __shared__ float red[256];
    red[t]=v0+v1; __syncthreads();
    for (int s=128;s>0;s>>=1){ if(t<s) red[t]+=red[t+s]; __syncthreads(); }
    const float mu = red[0]*(1.f/CDIM); __syncthreads();
    float d0=v0-mu, d1=v1-mu;
    red[t]=d0*d0+d1*d1; __syncthreads();
    for (int s=128;s>0;s>>=1){ if(t<s) red[t]+=red[t+s]; __syncthreads(); }
    const float inv = rsqrtf(red[0]*(1.f/CDIM)+1e-5f);
    float y0 = d0*inv*g[t]+bta[t];
    float y1 = d1*inv*g[t+256]+bta[t+256];
    bf16 h=__float2bfloat16(y0);
    g_yh[(size_t)row*CDIM+t]=h;
    g_yl[(size_t)row*CDIM+t]=__float2bfloat16(y0-__bfloat162float(h));
    h=__float2bfloat16(y1);
    g_yh[(size_t)row*CDIM+t+256]=h;
    g_yl[(size_t)row*CDIM+t+256]=__float2bfloat16(y1-__bfloat162float(h));
}

// ---------------- weight transpose + split (merged launches) ----------------
__device__ __forceinline__ void wsplit_body(float (*tile)[33],
    const float* __restrict__ W, bf16* __restrict__ Th, bf16* __restrict__ Tl,
    int K, int N, int k0, int n0, int tx, int ty)
{
#pragma unroll
    for (int i=0;i<32;i+=8)
        tile[ty+i][tx] = W[(size_t)(k0+ty+i)*N + n0+tx];
    __syncthreads();
#pragma unroll
    for (int i=0;i<32;i+=8){
        float v = tile[tx][ty+i];
        bf16 h=__float2bfloat16(v);
        Th[(size_t)(n0+ty+i)*K + k0+tx] = h;
        Tl[(size_t)(n0+ty+i)*K + k0+tx] = __float2bfloat16(v-__bfloat162float(h));
    }
}

// all 5 layers of qkv_w: grid (48, 16, 5)
__global__ void wsplit_qkv(const float* __restrict__ W, bf16* __restrict__ Th,
                           bf16* __restrict__ Tl)
{
    __shared__ float tile[32][33];
    const int l = blockIdx.z;
    wsplit_body(tile, W + (size_t)l*512*1536,
                Th + (size_t)l*1536*512, Tl + (size_t)l*1536*512,
                512, 1536, blockIdx.y*32, blockIdx.x*32, threadIdx.x, threadIdx.y);
}

// all 5 layers of fc1_w + fc2_w: grid (1024, 1, 5); first 512 tiles = fc1
__global__ void wsplit_fc(const float* __restrict__ W1, const float* __restrict__ W2,
                          bf16* __restrict__ T1h, bf16* __restrict__ T1l,
                          bf16* __restrict__ T2h, bf16* __restrict__ T2l)
{
    __shared__ float tile[32][33];
    const int l = blockIdx.z;
    int id = blockIdx.x;
    if (id < 512){
        // fc1: K=512, N=1024; tiles 32 (n) x 16 (k)
        wsplit_body(tile, W1 + (size_t)l*512*1024,
                    T1h + (size_t)l*1024*512, T1l + (size_t)l*1024*512,
                    512, 1024, (id>>5)*32, (id&31)*32, threadIdx.x, threadIdx.y);
    } else {
        id -= 512;
        // fc2: K=1024, N=512; tiles 16 (n) x 32 (k)
        wsplit_body(tile, W2 + (size_t)l*1024*512,
                    T2h + (size_t)l*512*1024, T2l + (size_t)l*512*1024,
                    1024, 512, (id>>4)*32, (id&15)*32, threadIdx.x, threadIdx.y);
    }
}

// ---------------------------------------------------------------------------
extern "C" void kernel_launch(void* const* d_in, const int* in_sizes, int n_in,
                              void* d_out, int out_size)
{
    const float* x_in  = (const float*)d_in[0];
    const float* qkv_w = (const float*)d_in[1];
    const float* qkv_b = (const float*)d_in[2];
    const float* ln_g  = (const float*)d_in[3];
    const float* ln_b  = (const float*)d_in[4];
    const float* fc1_w = (const float*)d_in[5];
    const float* fc1_b = (const float*)d_in[6];
    const float* fc2_w = (const float*)d_in[7];
    const float* fc2_b = (const float*)d_in[8];
    float* out = (float*)d_out;

    bf16 *wqh,*wql,*w1h,*w1l,*w2h,*w2l;
    cudaGetSymbolAddress((void**)&wqh, g_wqh);
    cudaGetSymbolAddress((void**)&wql, g_wql);
    cudaGetSymbolAddress((void**)&w1h, g_w1h);
    cudaGetSymbolAddress((void**)&w1l, g_w1l);
    cudaGetSymbolAddress((void**)&w2h, g_w2h);
    cudaGetSymbolAddress((void**)&w2l, g_w2l);

    cudaFuncSetAttribute(gemm_mma<0>, cudaFuncAttributeMaxDynamicSharedMemorySize, SMEMSZ);
    cudaFuncSetAttribute(gemm_mma<1>, cudaFuncAttributeMaxDynamicSharedMemorySize, SMEMSZ);
    cudaFuncSetAttribute(gemm_mma<2>, cudaFuncAttributeMaxDynamicSharedMemorySize, SMEMSZ);
    cudaFuncSetAttribute(gemm_mma<3>, cudaFuncAttributeMaxDynamicSharedMemorySize, SMEMSZ);
    cudaFuncSetAttribute(gemm_mma<4>, cudaFuncAttributeMaxDynamicSharedMemorySize, SMEMSZ);

    const dim3 thr(256);
    const dim3 tb(32,8);

    // weight prep: 2 launches total (all layers)
    wsplit_qkv<<<dim3(48,16,5), tb>>>(qkv_w, wqh, wql);
    wsplit_fc <<<dim3(1024,1,5), tb>>>(fc1_w, fc2_w, w1h, w1l, w2h, w2l);

    for (int l=0;l<NLAYER;l++){
        const float* src = (l==0) ? x_in : out;
        gemm_mma<0><<<dim3(12,128), thr, SMEMSZ>>>(src,
            wqh + (size_t)l*3*CDIM*CDIM, wql + (size_t)l*3*CDIM*CDIM,
            qkv_b + (size_t)l*3*CDIM, nullptr);
        gemm_mma<1><<<dim3(16,128), thr, SMEMSZ>>>(nullptr, nullptr, nullptr, nullptr, nullptr);
        softmax_k<<<MROWS, thr>>>();
        gemm_mma<2><<<dim3(4,128), thr, SMEMSZ>>>(nullptr, nullptr, nullptr, nullptr, out);
        layernorm_k<<<MROWS, thr>>>(out, ln_g + (size_t)l*CDIM, ln_b + (size_t)l*CDIM);
        gemm_mma<3><<<dim3(8,128), thr, SMEMSZ>>>(nullptr,
            w1h + (size_t)l*2*CDIM*CDIM, w1l + (size_t)l*2*CDIM*CDIM,
            fc1_b + (size_t)l*2*CDIM, nullptr);
        gemm_mma<4><<<dim3(4,128), thr, SMEMSZ>>>(nullptr,
            w2h + (size_t)l*2*CDIM*CDIM, w2l + (size_t)l*2*CDIM*CDIM,
            fc2_b + (size_t)l*CDIM, out);
    }
}

// round 12
// speedup vs baseline: 2.1748x; 1.0064x over previous
#include <cuda_runtime.h>
#include <cuda_bf16.h>
#include <math.h>
#include <stdint.h>

typedef __nv_bfloat16 bf16;

#define CDIM   512
#define NTOK   2048
#define BATCH  8
#define NLAYER 5
#define MROWS  16384
#define NN     ((size_t)NTOK*NTOK)

// ---------------- scratch (device globals; allocation-free rule) -----------
__device__ float g_S [(size_t)BATCH*NN];
__device__ bf16  g_sh[(size_t)BATCH*NN];
__device__ bf16  g_sl[(size_t)BATCH*NN];
__device__ bf16  g_qh[(size_t)MROWS*CDIM];
__device__ bf16  g_ql[(size_t)MROWS*CDIM];
__device__ bf16  g_kh[(size_t)MROWS*CDIM];
__device__ bf16  g_kl[(size_t)MROWS*CDIM];
__device__ bf16  g_vth[(size_t)MROWS*CDIM];   // V^T: [b][c][n]
__device__ bf16  g_vtl[(size_t)MROWS*CDIM];
__device__ bf16  g_yh[(size_t)MROWS*CDIM];
__device__ bf16  g_yl[(size_t)MROWS*CDIM];
__device__ bf16  g_hh[(size_t)MROWS*2*CDIM];
__device__ bf16  g_hl[(size_t)MROWS*2*CDIM];
__device__ bf16  g_wqh[(size_t)NLAYER*3*CDIM*CDIM];   // W^T [N][K] hi/lo
__device__ bf16  g_wql[(size_t)NLAYER*3*CDIM*CDIM];
__device__ bf16  g_w1h[(size_t)NLAYER*2*CDIM*CDIM];
__device__ bf16  g_w1l[(size_t)NLAYER*2*CDIM*CDIM];
__device__ bf16  g_w2h[(size_t)NLAYER*2*CDIM*CDIM];
__device__ bf16  g_w2l[(size_t)NLAYER*2*CDIM*CDIM];

// ---------------- helpers --------------------------------------------------
__device__ __forceinline__ uint32_t s2u(const void* p){
    uint32_t a;
    asm("{ .reg .u64 t; cvta.to.shared.u64 t, %1; cvt.u32.u64 %0, t; }" : "=r"(a) : "l"(p));
    return a;
}
__device__ __forceinline__ void cpa16(uint32_t s, const void* g){
    asm volatile("cp.async.cg.shared.global [%0], [%1], 16;" :: "r"(s), "l"(g));
}
__device__ __forceinline__ void ldmx4(uint32_t* r, uint32_t addr){
    asm volatile("ldmatrix.sync.aligned.m8n8.x4.shared.b16 {%0,%1,%2,%3}, [%4];"
        : "=r"(r[0]), "=r"(r[1]), "=r"(r[2]), "=r"(r[3]) : "r"(addr));
}
__device__ __forceinline__ void mma16816(float* c, const uint32_t* a, const uint32_t* b){
    asm volatile("mma.sync.aligned.m16n8k16.row.col.f32.bf16.bf16.f32 "
        "{%0,%1,%2,%3}, {%4,%5,%6,%7}, {%8,%9}, {%0,%1,%2,%3};"
        : "+f"(c[0]), "+f"(c[1]), "+f"(c[2]), "+f"(c[3])
        : "r"(a[0]), "r"(a[1]), "r"(a[2]), "r"(a[3]), "r"(b[0]), "r"(b[1]));
}
__device__ __forceinline__ void split2(float v0, float v1, uint32_t& hp, uint32_t& lp){
    bf16 h0=__float2bfloat16(v0), h1=__float2bfloat16(v1);
    bf16 l0=__float2bfloat16(v0-__bfloat162float(h0));
    bf16 l1=__float2bfloat16(v1-__bfloat162float(h1));
    hp = (uint32_t)__bfloat16_as_ushort(h0) | ((uint32_t)__bfloat16_as_ushort(h1)<<16);
    lp = (uint32_t)__bfloat16_as_ushort(l0) | ((uint32_t)__bfloat16_as_ushort(l1)<<16);
}

// smem: 4 stages x (Ah|Al|Bh|Bl), each half = 128 rows x 40 bf16 (32 data + pad)
// row stride 80B -> ldmatrix 8-row access is bank-conflict-free.
#define ROWB   80
#define HALF_B 10240
#define STG_B  40960
#define NSTG   4
#define SMEMSZ (NSTG*STG_B)
#define NTHR   512

// ---------------- stage loader (512 threads) --------------------------------
template<int MODE>
__device__ __forceinline__ void load_stage(char* smc, uint32_t sb, int s, int k0, int t,
    const float* Afp, const bf16* Ah, const bf16* Al, const bf16* Bh, const bf16* Bl,
    int rA0, int c0)
{
    constexpr int LDA = (MODE==2)?2048:((MODE==4)?1024:512);
    const uint32_t st = sb + (uint32_t)s*STG_B;
    char* sd = smc + s*STG_B;
    if (MODE==0){
        // A: fp32 -> split in regs -> STS; 128 rows x 4 chunks of 8 = 512 tasks
        {
            int row=t>>2, kq=t&3;
            const float* src = Afp + (size_t)(rA0+row)*512 + k0 + kq*8;
            float4 u0=*(const float4*)src, u1=*(const float4*)(src+4);
            float vv[8]={u0.x,u0.y,u0.z,u0.w,u1.x,u1.y,u1.z,u1.w};
            __align__(16) bf16 hh[8]; __align__(16) bf16 ll[8];
#pragma unroll
            for (int j2=0;j2<8;j2++){
                hh[j2]=__float2bfloat16(vv[j2]);
                ll[j2]=__float2bfloat16(vv[j2]-__bfloat162float(hh[j2]));
            }
            char* d = sd + row*ROWB + kq*16;
            *(uint4*)d            = *(uint4*)hh;
            *(uint4*)(d + HALF_B) = *(uint4*)ll;
        }
        // B: pre-split weights via cp.async; 2 halves x 512 chunks / 512 thr
#pragma unroll
        for (int i=0;i<2;i++){
            int f=t+i*512, hf=f>>9, idx=f&511, row=idx>>2, kq=idx&3;
            const bf16* src = (hf? Bl:Bh) + (size_t)(c0+row)*512 + k0 + kq*8;
            cpa16(st + 2*HALF_B + hf*HALF_B + row*ROWB + kq*16, src);
        }
    } else {
        // 4 halves x 512 chunks / 512 thr = 4 per thread
#pragma unroll
        for (int i=0;i<4;i++){
            int f=t+i*512, hf=f>>9, idx=f&511, row=idx>>2, kq=idx&3;
            const bf16* base = (hf==0)?Ah:((hf==1)?Al:((hf==2)?Bh:Bl));
            int r = (hf<2)?(rA0+row):(c0+row);
            cpa16(st + hf*HALF_B + row*ROWB + kq*16, base + (size_t)r*LDA + k0 + kq*8);
        }
    }
    asm volatile("cp.async.commit_group;" ::: "memory");
}

// ---------------- per-stage compute (warp tile 32x32, 2 k-steps of 16) ------
__device__ __forceinline__ void compute_stage(uint32_t st, int wm0, int wn0, int lane,
                                              float acc[2][4][4])
{
#pragma unroll
    for (int kk=0; kk<32; kk+=16){
        uint32_t ah[2][4], al[2][4], bh[4][2], bl[4][2];
        const uint32_t acol = (uint32_t)(kk + (lane>>4)*8)*2;
#pragma unroll
        for (int i=0;i<2;i++){
            uint32_t ra = st + (uint32_t)(wm0 + i*16 + (lane&15))*ROWB + acol;
            ldmx4(ah[i], ra);
            ldmx4(al[i], ra + HALF_B);
        }
#pragma unroll
        for (int p=0;p<2;p++){
            uint32_t rb_ = st + 2*HALF_B
                         + (uint32_t)(wn0 + p*16 + (lane&7) + (lane>>4)*8)*ROWB
                         + (uint32_t)(kk + ((lane>>3)&1)*8)*2;
            uint32_t r4[4];
            ldmx4(r4, rb_);
            bh[p*2][0]=r4[0]; bh[p*2][1]=r4[1]; bh[p*2+1][0]=r4[2]; bh[p*2+1][1]=r4[3];
            ldmx4(r4, rb_ + HALF_B);
            bl[p*2][0]=r4[0]; bl[p*2][1]=r4[1]; bl[p*2+1][0]=r4[2]; bl[p*2+1][1]=r4[3];
        }
#pragma unroll
        for (int i=0;i<2;i++)
#pragma unroll
            for (int j=0;j<4;j++){
                mma16816(acc[i][j], ah[i], bh[j]);
                mma16816(acc[i][j], ah[i], bl[j]);
                mma16816(acc[i][j], al[i], bh[j]);
            }
    }
}

// ---------------- GEMM kernel ------------------------------------------------
// MODE 0: qkv   A=fp32 src (split on fly), B=WqT; epi: +bias -> split Q/K/V^T
// MODE 1: score A=Q(split),  B=K(split per-batch); epi: *scale -> S fp32 (tile skip)
// MODE 2: attnv A=S(split),  B=V^T(split per-batch); epi -> Out fp32 (k-trunc)
// MODE 3: fc1   A=y(split),  B=W1T; epi: +bias, gelu -> split h
// MODE 4: fc2   A=h(split),  B=W2T; epi: Out += v+bias
template<int MODE>
__global__ __launch_bounds__(NTHR,1)
void gemm_mma(const float* __restrict__ Afp, const bf16* __restrict__ Bwh,
              const bf16* __restrict__ Bwl, const float* __restrict__ bias,
              float* __restrict__ Out)
{
    const int t=threadIdx.x, lane=t&31, warp=t>>5;      // 16 warps: 4 (m) x 4 (n)
    const int wm0=(warp&3)*32, wn0=(warp>>2)*32;
    const int bx=blockIdx.x, by=blockIdx.y;
    const int rb=by&15, b=by>>4;
    if (MODE==1){ if (rb<8){ if (bx>=8) return; } else { if (bx>rb) return; } }
    const int c0=bx*128;
    const int rA0=(MODE==2)?(rb*128):(by*128);
    int nT;
    if (MODE==2)      nT = ((rb<8)?1024:((rb+1)*128)) >> 5;
    else if (MODE==4) nT = 32;
    else              nT = 16;

    const bf16 *Ah=nullptr,*Al=nullptr,*Bh=Bwh,*Bl=Bwl;
    if (MODE==1){ Ah=g_qh; Al=g_ql;
                  Bh=g_kh+(size_t)b*NTOK*CDIM; Bl=g_kl+(size_t)b*NTOK*CDIM; }
    if (MODE==2){ Ah=g_sh+(size_t)b*NN; Al=g_sl+(size_t)b*NN;
                  Bh=g_vth+(size_t)b*CDIM*NTOK; Bl=g_vtl+(size_t)b*CDIM*NTOK; }
    if (MODE==3){ Ah=g_yh; Al=g_yl; }
    if (MODE==4){ Ah=g_hh; Al=g_hl; }

    extern __shared__ char smc[];
    const uint32_t sb = s2u(smc);

    float acc[2][4][4];
#pragma unroll
    for (int i=0;i<2;i++)
#pragma unroll
        for (int j=0;j<4;j++)
#pragma unroll
            for (int q=0;q<4;q++) acc[i][j][q]=0.f;

    // prologue: prefetch 3 stages (nT >= 16 always)
    load_stage<MODE>(smc, sb, 0, 0,  t, Afp, Ah, Al, Bh, Bl, rA0, c0);
    load_stage<MODE>(smc, sb, 1, 32, t, Afp, Ah, Al, Bh, Bl, rA0, c0);
    load_stage<MODE>(smc, sb, 2, 64, t, Afp, Ah, Al, Bh, Bl, rA0, c0);
    for (int ti=0; ti<nT; ti++){
        const int rem = nT - 1 - ti;
        if (rem >= 2)      asm volatile("cp.async.wait_group 2;" ::: "memory");
        else if (rem == 1) asm volatile("cp.async.wait_group 1;" ::: "memory");
        else               asm volatile("cp.async.wait_group 0;" ::: "memory");
        __syncthreads();   // stage ti visible; slot (ti+3)&3 free (consumed at ti-1)
        if (ti+3 < nT)
            load_stage<MODE>(smc, sb, (ti+3)&3, (ti+3)*32, t, Afp, Ah, Al, Bh, Bl, rA0, c0);
        compute_stage(sb + (uint32_t)(ti&3)*STG_B, wm0, wn0, lane, acc);
    }

    // ---------------- epilogue ----------------
    const int lr=lane>>2, lc=(lane&3)*2;
#pragma unroll
    for (int i=0;i<2;i++){
#pragma unroll
        for (int h=0;h<2;h++){
            const int r  = wm0 + i*16 + lr + h*8;
            const int gr = by*128 + r;
#pragma unroll
            for (int j=0;j<4;j++){
                const int c = c0 + wn0 + j*8 + lc;
                float v0=acc[i][j][h*2], v1=acc[i][j][h*2+1];
                if (MODE==0){
                    v0 += bias[c]; v1 += bias[c+1];
                    if (c<1024){
                        uint32_t ph, pl; split2(v0,v1,ph,pl);
                        if (c<512){
                            *(uint32_t*)&g_qh[(size_t)gr*512+c]=ph;
                            *(uint32_t*)&g_ql[(size_t)gr*512+c]=pl;
                        } else {
                            *(uint32_t*)&g_kh[(size_t)gr*512+(c-512)]=ph;
                            *(uint32_t*)&g_kl[(size_t)gr*512+(c-512)]=pl;
                        }
                    } else {
                        int cv=c-1024, bb=gr>>11, n=gr&2047;
                        bf16 h0=__float2bfloat16(v0);
                        bf16 l0=__float2bfloat16(v0-__bfloat162float(h0));
                        bf16 h1=__float2bfloat16(v1);
                        bf16 l1=__float2bfloat16(v1-__bfloat162float(h1));
                        size_t o0=((size_t)bb*512+cv)*2048+n;
                        size_t o1=((size_t)bb*512+cv+1)*2048+n;
                        g_vth[o0]=h0; g_vtl[o0]=l0;
                        g_vth[o1]=h1; g_vtl[o1]=l1;
                    }
                } else if (MODE==1){
                    const int orow = rb*128 + r;
                    float2 vv = { v0*0.044194173824159216f, v1*0.044194173824159216f };
                    *(float2*)&g_S[(size_t)b*NN + (size_t)orow*2048 + c] = vv;
                } else if (MODE==2){
                    float2 vv = { v0, v1 };
                    *(float2*)&Out[(size_t)gr*512 + c] = vv;
                } else if (MODE==3){
                    v0+=bias[c]; v1+=bias[c+1];
                    v0 = 0.5f*v0*(1.f+erff(v0*0.70710678118654752f));
                    v1 = 0.5f*v1*(1.f+erff(v1*0.70710678118654752f));
                    uint32_t ph,pl; split2(v0,v1,ph,pl);
                    *(uint32_t*)&g_hh[(size_t)gr*1024+c]=ph;
                    *(uint32_t*)&g_hl[(size_t)gr*1024+c]=pl;
                } else {
                    float2* p=(float2*)&Out[(size_t)gr*512+c];
                    float2 o=*p;
                    o.x += v0 + bias[c];
                    o.y += v1 + bias[c+1];
                    *p=o;
                }
            }
        }
    }
}

// ---------------- masked softmax: fp32 S row -> split-bf16 ------------------
__global__ __launch_bounds__(256)
void softmax_k()
{
    const int row = blockIdx.x;
    const int b = row >> 11, i = row & (NTOK-1);
    const int limit = (i < 1024) ? 1024 : (i+1);
    const int kmax  = (i < 1024) ? 1024 : (((i>>7)+1)<<7);
    const float* p = g_S + (size_t)b*NN + (size_t)i*NTOK;
    bf16* ph = g_sh + (size_t)b*NN + (size_t)i*NTOK;
    bf16* pl = g_sl + (size_t)b*NN + (size_t)i*NTOK;
    const int t = threadIdx.x;
    float vals[8]; float m = -1e30f;
#pragma unroll
    for (int j=0;j<8;j++){ int idx=t+j*256; vals[j]=(idx<limit)?p[idx]:-1e30f; m=fmaxf(m,vals[j]); }
    __shared__ float red[256];
    red[t]=m; __syncthreads();
    for (int s=128;s>0;s>>=1){ if(t<s) red[t]=fmaxf(red[t],red[t+s]); __syncthreads(); }
    m = red[0]; __syncthreads();
    float sum=0.f;
#pragma unroll
    for (int j=0;j<8;j++){ int idx=t+j*256; if(idx<limit){ vals[j]=expf(vals[j]-m); sum+=vals[j]; } else vals[j]=0.f; }
    red[t]=sum; __syncthreads();
    for (int s=128;s>0;s>>=1){ if(t<s) red[t]+=red[t+s]; __syncthreads(); }
    const float inv = 1.f/red[0];
#pragma unroll
    for (int j=0;j<8;j++){
        int idx=t+j*256;
        if (idx<kmax){
            float v = vals[j]*inv;
            bf16 h=__float2bfloat16(v);
            bf16 l=__float2bfloat16(v-__bfloat162float(h));
            ph[idx]=h; pl[idx]=l;
        }
    }
}

// ---------------- LayerNorm -> split-bf16 y ---------------------------------
__global__ __launch_bounds__(256)
void layernorm_k(const float* __restrict__ X, const float* __restrict__ g,
                 const float* __restrict__ bta)
{
    const int row = blockIdx.x;
    const float* x = X + (size_t)row*CDIM;
    const int t = threadIdx.x;
    float v0=x[t], v1=x[t+256];
    __shared__ float red[256];
    red[t]=v0+v1; __syncthreads();
    for (int s=128;s>0;s>>=1){ if(t<s) red[t]+=red[t+s]; __syncthreads(); }
    const float mu = red[0]*(1.f/CDIM); __syncthreads();
    float d0=v0-mu, d1=v1-mu;
    red[t]=d0*d0+d1*d1; __syncthreads();
    for (int s=128;s>0;s>>=1){ if(t<s) red[t]+=red[t+s]; __syncthreads(); }
    const float inv = rsqrtf(red[0]*(1.f/CDIM)+1e-5f);
    float y0 = d0*inv*g[t]+bta[t];
    float y1 = d1*inv*g[t+256]+bta[t+256];
    bf16 h=__float2bfloat16(y0);
    g_yh[(size_t)row*CDIM+t]=h;
    g_yl[(size_t)row*CDIM+t]=__float2bfloat16(y0-__bfloat162float(h));
    h=__float2bfloat16(y1);
    g_yh[(size_t)row*CDIM+t+256]=h;
    g_yl[(size_t)row*CDIM+t+256]=__float2bfloat16(y1-__bfloat162float(h));
}

// ---------------- weight transpose + split (merged launches) ----------------
__device__ __forceinline__ void wsplit_body(float (*tile)[33],
    const float* __restrict__ W, bf16* __restrict__ Th, bf16* __restrict__ Tl,
    int K, int N, int k0, int n0, int tx, int ty)
{
#pragma unroll
    for (int i=0;i<32;i+=8)
        tile[ty+i][tx] = W[(size_t)(k0+ty+i)*N + n0+tx];
    __syncthreads();
#pragma unroll
    for (int i=0;i<32;i+=8){
        float v = tile[tx][ty+i];
        bf16 h=__float2bfloat16(v);
        Th[(size_t)(n0+ty+i)*K + k0+tx] = h;
        Tl[(size_t)(n0+ty+i)*K + k0+tx] = __float2bfloat16(v-__bfloat162float(h));
    }
}

// all 5 layers of qkv_w: grid (48, 16, 5)
__global__ void wsplit_qkv(const float* __restrict__ W, bf16* __restrict__ Th,
                           bf16* __restrict__ Tl)
{
    __shared__ float tile[32][33];
    const int l = blockIdx.z;
    wsplit_body(tile, W + (size_t)l*512*1536,
                Th + (size_t)l*1536*512, Tl + (size_t)l*1536*512,
                512, 1536, blockIdx.y*32, blockIdx.x*32, threadIdx.x, threadIdx.y);
}

// all 5 layers of fc1_w + fc2_w: grid (1024, 1, 5); first 512 tiles = fc1
__global__ void wsplit_fc(const float* __restrict__ W1, const float* __restrict__ W2,
                          bf16* __restrict__ T1h, bf16* __restrict__ T1l,
                          bf16* __restrict__ T2h, bf16* __restrict__ T2l)
{
    __shared__ float tile[32][33];
    const int l = blockIdx.z;
    int id = blockIdx.x;
    if (id < 512){
        wsplit_body(tile, W1 + (size_t)l*512*1024,
                    T1h + (size_t)l*1024*512, T1l + (size_t)l*1024*512,
                    512, 1024, (id>>5)*32, (id&31)*32, threadIdx.x, threadIdx.y);
    } else {
        id -= 512;
        wsplit_body(tile, W2 + (size_t)l*1024*512,
                    T2h + (size_t)l*512*1024, T2l + (size_t)l*512*1024,
                    1024, 512, (id>>4)*32, (id&15)*32, threadIdx.x, threadIdx.y);
    }
}

// ---------------------------------------------------------------------------
extern "C" void kernel_launch(void* const* d_in, const int* in_sizes, int n_in,
                              void* d_out, int out_size)
{
    const float* x_in  = (const float*)d_in[0];
    const float* qkv_w = (const float*)d_in[1];
    const float* qkv_b = (const float*)d_in[2];
    const float* ln_g  = (const float*)d_in[3];
    const float* ln_b  = (const float*)d_in[4];
    const float* fc1_w = (const float*)d_in[5];
    const float* fc1_b = (const float*)d_in[6];
    const float* fc2_w = (const float*)d_in[7];
    const float* fc2_b = (const float*)d_in[8];
    float* out = (float*)d_out;

    bf16 *wqh,*wql,*w1h,*w1l,*w2h,*w2l;
    cudaGetSymbolAddress((void**)&wqh, g_wqh);
    cudaGetSymbolAddress((void**)&wql, g_wql);
    cudaGetSymbolAddress((void**)&w1h, g_w1h);
    cudaGetSymbolAddress((void**)&w1l, g_w1l);
    cudaGetSymbolAddress((void**)&w2h, g_w2h);
    cudaGetSymbolAddress((void**)&w2l, g_w2l);

    cudaFuncSetAttribute(gemm_mma<0>, cudaFuncAttributeMaxDynamicSharedMemorySize, SMEMSZ);
    cudaFuncSetAttribute(gemm_mma<1>, cudaFuncAttributeMaxDynamicSharedMemorySize, SMEMSZ);
    cudaFuncSetAttribute(gemm_mma<2>, cudaFuncAttributeMaxDynamicSharedMemorySize, SMEMSZ);
    cudaFuncSetAttribute(gemm_mma<3>, cudaFuncAttributeMaxDynamicSharedMemorySize, SMEMSZ);
    cudaFuncSetAttribute(gemm_mma<4>, cudaFuncAttributeMaxDynamicSharedMemorySize, SMEMSZ);

    const dim3 thr(NTHR);
    const dim3 thr256(256);
    const dim3 tb(32,8);

    // weight prep: 2 launches total (all layers)
    wsplit_qkv<<<dim3(48,16,5), tb>>>(qkv_w, wqh, wql);
    wsplit_fc <<<dim3(1024,1,5), tb>>>(fc1_w, fc2_w, w1h, w1l, w2h, w2l);

    for (int l=0;l<NLAYER;l++){
        const float* src = (l==0) ? x_in : out;
        gemm_mma<0><<<dim3(12,128), thr, SMEMSZ>>>(src,
            wqh + (size_t)l*3*CDIM*CDIM, wql + (size_t)l*3*CDIM*CDIM,
            qkv_b + (size_t)l*3*CDIM, nullptr);
        gemm_mma<1><<<dim3(16,128), thr, SMEMSZ>>>(nullptr, nullptr, nullptr, nullptr, nullptr);
        softmax_k<<<MROWS, thr256>>>();
        gemm_mma<2><<<dim3(4,128), thr, SMEMSZ>>>(nullptr, nullptr, nullptr, nullptr, out);
        layernorm_k<<<MROWS, thr256>>>(out, ln_g + (size_t)l*CDIM, ln_b + (size_t)l*CDIM);
        gemm_mma<3><<<dim3(8,128), thr, SMEMSZ>>>(nullptr,
            w1h + (size_t)l*2*CDIM*CDIM, w1l + (size_t)l*2*CDIM*CDIM,
            fc1_b + (size_t)l*2*CDIM, nullptr);
        gemm_mma<4><<<dim3(4,128), thr, SMEMSZ>>>(nullptr,
            w2h + (size_t)l*2*CDIM*CDIM, w2l + (size_t)l*2*CDIM*CDIM,
            fc2_b + (size_t)l*CDIM, out);
    }
}